// round 16
// baseline (speedup 1.0000x reference)
#include <cuda_runtime.h>
#include <math.h>

// FeatureNormMagOnline — FUSED single-read chained scan (decoupled lookback).
// EMA s_t = (1-a) s_{t-1} + a p_t ; chunk L: s_end = (1-a)^L s_start + c.
// Roofline logic: two-pass designs read the input twice (198MB => ~30us floor,
// R6 measured 31.9). This kernel reads the input ONCE (139MB => ~21us floor):
//   stage chunk in SMEM -> scan from zero -> publish partial+flag ->
//   lookback (<=49 lower-ID flags) -> fold seeds -> rescan SMEM -> write out.
// Occupancy fix vs R9/R10 failures: LCH=20 -> SMEM 41.1KB -> 5 CTA/SM,
// 45 warps/SM (R9 had 2 CTA/18 warps; R10 spilled at 96 regs).

#define B_   16
#define C_   2
#define T_   1000
#define F_   257
#define BC_  (B_ * C_)     // 32
#define NCH  50
#define LCH  20            // NCH * LCH == T_
#define NTHR 288           // 9 warps; f = tid, guard f < 257

static const long long RES_ELEMS = (long long)B_ * C_ * T_ * F_ * 2;  // 16,448,000
static const int NSEQ = BC_ * F_;                  // 8224
static const int SMEM_BYTES = LCH * F_ * 2 * 4;    // 41,120 B

__device__ float g_part[NCH * BC_ * F_];   // partial EMA per (ch, bc, f)
__device__ int   g_flag[NCH * BC_];        // publish flags (reset each replay)

__global__ void init_flags()
{
    int i = blockIdx.x * blockDim.x + threadIdx.x;
    if (i < NCH * BC_) g_flag[i] = 0;
}

__global__ void __launch_bounds__(NTHR, 5)
ema_fused_lookback(const float* __restrict__ in,
                   const float* __restrict__ weights,
                   const float* __restrict__ bias,
                   const float* __restrict__ alpha,
                   const float* __restrict__ s1,
                   float* __restrict__ out,
                   float* __restrict__ s_last_out)
{
    extern __shared__ float2 sx[];          // [LCH][F_]

    const int tid = threadIdx.x;
    const int bid = blockIdx.x;
    const int ch  = bid / BC_;              // ch-major: low ch = low block ID
    const int bc  = bid % BC_;
    const int c   = bc % C_;

    // ── stage chunk into SMEM: coalesced linear copy, high MLP ─────────────
    const float2* __restrict__ src =
        (const float2*)in + ((size_t)bc * T_ + (size_t)ch * LCH) * F_;
    #pragma unroll 6
    for (int i = tid; i < LCH * F_; i += NTHR)
        sx[i] = src[i];
    __syncthreads();

    const int  f     = tid;
    const bool valid = (f < F_);

    float a = 0.f, oma = 1.f, wgt = 0.f, bb = 0.f;
    if (valid) {
        a   = 1.0f / (1.0f + __expf(-alpha[c * F_ + f]));
        oma = 1.0f - a;
        wgt = weights[c * F_ + f];
        bb  = bias[c * F_ + f];
    }

    // ── phase 1: scan from zero over SMEM, publish partial ─────────────────
    float s = 0.0f;
    if (valid) {
        #pragma unroll
        for (int t = 0; t < LCH; ++t) {
            float2 x = sx[t * F_ + f];
            float p  = fmaf(x.x, x.x, x.y * x.y);
            s = fmaf(oma, s, a * p);
        }
        g_part[(ch * BC_ + bc) * F_ + f] = s;
    }
    __threadfence();
    __syncthreads();
    if (tid == 0) atomicExch(&g_flag[ch * BC_ + bc], 1);

    // ── lookback: wait on all predecessor chunks of this bc ────────────────
    if (tid < ch) {                          // <=49 lanes poll (2 warps max)
        volatile int* fl = &g_flag[tid * BC_ + bc];
        while (*fl == 0) { }
    }
    __syncthreads();
    __threadfence();                         // acquire: partials now visible

    // ── fold partials -> exact chunk-start seed (8-batched prefetch) ───────
    float s0 = 0.0f;
    if (valid) {
        s0 = s1[bc * F_ + f];
        float x2  = oma * oma;               // oma^20 = oma^16 * oma^4
        float x4  = x2 * x2;
        float x8  = x4 * x4;
        float x16 = x8 * x8;
        float omaL = x16 * x4;
        for (int base = 0; base < ch; base += 8) {
            float p[8];
            #pragma unroll
            for (int k = 0; k < 8; ++k) {    // independent L2 loads
                int i = base + k;
                p[k] = (i < ch) ? g_part[(i * BC_ + bc) * F_ + f] : 0.0f;
            }
            #pragma unroll
            for (int k = 0; k < 8; ++k) {
                int i = base + k;
                if (i < ch) s0 = fmaf(omaL, s0, p[k]);
            }
        }
    }

    // ── phase 2: rescan SMEM with exact seed, write output ─────────────────
    if (valid) {
        float2* __restrict__ outp =
            (float2*)out + ((size_t)bc * T_ + (size_t)ch * LCH) * F_ + f;
        s = s0;
        #pragma unroll
        for (int t = 0; t < LCH; ++t) {
            float2 x = sx[t * F_ + f];
            float p  = fmaf(x.x, x.x, x.y * x.y);
            s = fmaf(oma, s, a * p);
            // wgt/(sqrt(s)+1e-8) via one rsqrt: rel err (1e-8*r)^2, negligible
            float r   = rsqrtf(fmaxf(s, 1e-24f));
            float inv = wgt * r * fmaf(-1e-8f, r, 1.0f);
            float2 o;
            o.x = fmaf(x.x, inv, bb);
            o.y = fmaf(x.y, inv, bb);
            __stcs(outp + (size_t)t * F_, o);
        }
        if (ch == NCH - 1 && s_last_out)
            s_last_out[bc * F_ + f] = s;
    }
}

extern "C" void kernel_launch(void* const* d_in, const int* in_sizes, int n_in,
                              void* d_out, int out_size)
{
    const float* in      = (const float*)d_in[0];
    const float* weights = (const float*)d_in[1];
    const float* bias    = (const float*)d_in[2];
    const float* alpha   = (const float*)d_in[3];
    const float* s1      = (const float*)d_in[4];

    float* out = (float*)d_out;
    float* s_last = nullptr;
    if ((long long)out_size >= RES_ELEMS + NSEQ)
        s_last = out + RES_ELEMS;

    init_flags<<<(NCH * BC_ + 255) / 256, 256>>>();
    ema_fused_lookback<<<NCH * BC_, NTHR, SMEM_BYTES>>>(
        in, weights, bias, alpha, s1, out, s_last);
}

// round 17
// speedup vs baseline: 1.6377x; 1.6377x over previous
#include <cuda_runtime.h>
#include <math.h>

// FeatureNormMagOnline — two-kernel chunked scan, tuned (R6 structure).
// EMA s_t = (1-a) s_{t-1} + a p_t ; chunk L: s_end = (1-a)^L s_start + c.
//   pass1: per (bc,ch,f) partial EMA from zero over LCH=20 (batch fully
//          register-resident: 20 independent LDG.64 in flight, regs~56).
//   pass2: per (bc,ch,f): issue 20 input loads first, fold <=49 partials
//          (8-batched L2 loads) into the exact seed, then scan+normalize.
//          ONE rsqrt per step: inv = w*r*(1-1e-8*r), rel err (1e-8*r)^2.
// Within a replay pass1 leaves the 66MB input L2-resident (126MB L2), so
// pass2's re-read is mostly L2-served; stores are evict-first (__stcs).
// Lookback/fused variants measured 42-58us across R9/R10/R16 — abandoned.

#define B_   16
#define C_   2
#define T_   1000
#define F_   257
#define BC_  (B_ * C_)     // 32
#define NCH  50
#define LCH  20            // NCH * LCH == T_

static const long long RES_ELEMS = (long long)B_ * C_ * T_ * F_ * 2;  // 16,448,000
static const int NSEQ = BC_ * F_;            // 8224
static const int NIT  = BC_ * NCH * F_;      // 411,200 items per pass

__device__ float g_part[NCH * BC_ * F_];     // partial EMA per (ch, bc, f)

// ── pass 1: chunk partials from zero ─────────────────────────────────────────
__global__ void __launch_bounds__(256)
pass1_partials(const float* __restrict__ in,
               const float* __restrict__ alpha)
{
    int w = blockIdx.x * 256 + threadIdx.x;
    if (w >= NIT) return;
    int f  = w % F_;
    int q  = w / F_;
    int ch = q % NCH;
    int bc = q / NCH;
    int c  = bc % C_;

    float a   = 1.0f / (1.0f + __expf(-alpha[c * F_ + f]));
    float oma = 1.0f - a;

    const float2* __restrict__ inp =
        (const float2*)in + ((size_t)bc * T_ + (size_t)ch * LCH) * F_ + f;

    float2 x[LCH];
    #pragma unroll
    for (int t = 0; t < LCH; ++t)            // 20 independent LDG.64 in flight
        x[t] = inp[(size_t)t * F_];

    float s = 0.0f;
    #pragma unroll
    for (int t = 0; t < LCH; ++t) {
        float p = fmaf(x[t].x, x[t].x, x[t].y * x[t].y);
        s = fmaf(oma, s, a * p);
    }
    g_part[(ch * BC_ + bc) * F_ + f] = s;
}

// ── pass 2: seed fold + rescan + normalize + store ──────────────────────────
__global__ void __launch_bounds__(256)
pass2_scan_out(const float* __restrict__ in,
               const float* __restrict__ weights,
               const float* __restrict__ bias,
               const float* __restrict__ alpha,
               const float* __restrict__ s1,
               float* __restrict__ out,
               float* __restrict__ s_last_out)
{
    int w = blockIdx.x * 256 + threadIdx.x;
    if (w >= NIT) return;
    int f  = w % F_;
    int q  = w / F_;
    int ch = q % NCH;
    int bc = q / NCH;
    int c  = bc % C_;
    int cf = c * F_ + f;

    // issue the long-latency input batch FIRST (20 independent LDG.64)
    const float2* __restrict__ inp =
        (const float2*)in + ((size_t)bc * T_ + (size_t)ch * LCH) * F_ + f;
    float2 x[LCH];
    #pragma unroll
    for (int t = 0; t < LCH; ++t)
        x[t] = inp[(size_t)t * F_];

    float a   = 1.0f / (1.0f + __expf(-alpha[cf]));
    float oma = 1.0f - a;
    float wgt = weights[cf];
    float bb  = bias[cf];

    // oma^20 = oma^16 * oma^4 (5 muls, replaces powf)
    float y2  = oma * oma;
    float y4  = y2 * y2;
    float y8  = y4 * y4;
    float y16 = y8 * y8;
    float omaL = y16 * y4;

    // fold partials of chunks [0, ch) into the exact seed, 8-batched
    float s = s1[bc * F_ + f];
    for (int base = 0; base < ch; base += 8) {
        float p[8];
        #pragma unroll
        for (int k = 0; k < 8; ++k) {        // independent L2 loads
            int i = base + k;
            p[k] = (i < ch) ? g_part[(i * BC_ + bc) * F_ + f] : 0.0f;
        }
        #pragma unroll
        for (int k = 0; k < 8; ++k) {
            int i = base + k;
            if (i < ch) s = fmaf(omaL, s, p[k]);
        }
    }

    // scan chunk with exact seed, normalize, store
    float2* __restrict__ outp =
        (float2*)out + ((size_t)bc * T_ + (size_t)ch * LCH) * F_ + f;
    #pragma unroll
    for (int t = 0; t < LCH; ++t) {
        float p = fmaf(x[t].x, x[t].x, x[t].y * x[t].y);
        s = fmaf(oma, s, a * p);
        // wgt/(sqrt(s)+1e-8) via one rsqrt: r=1/sqrt(s), inv=wgt*r*(1-1e-8*r)
        float r   = rsqrtf(fmaxf(s, 1e-24f));
        float inv = wgt * r * fmaf(-1e-8f, r, 1.0f);
        float2 o;
        o.x = fmaf(x[t].x, inv, bb);
        o.y = fmaf(x[t].y, inv, bb);
        __stcs(outp + (size_t)t * F_, o);    // evict-first: spare input lines
    }

    if (ch == NCH - 1 && s_last_out)
        s_last_out[bc * F_ + f] = s;
}

extern "C" void kernel_launch(void* const* d_in, const int* in_sizes, int n_in,
                              void* d_out, int out_size)
{
    const float* in      = (const float*)d_in[0];
    const float* weights = (const float*)d_in[1];
    const float* bias    = (const float*)d_in[2];
    const float* alpha   = (const float*)d_in[3];
    const float* s1      = (const float*)d_in[4];

    float* out = (float*)d_out;
    float* s_last = nullptr;
    if ((long long)out_size >= RES_ELEMS + NSEQ)
        s_last = out + RES_ELEMS;

    int g = (NIT + 255) / 256;   // 1607 blocks per pass

    pass1_partials<<<g, 256>>>(in, alpha);
    pass2_scan_out<<<g, 256>>>(in, weights, bias, alpha, s1, out, s_last);
}